// round 16
// baseline (speedup 1.0000x reference)
#include <cuda_runtime.h>
#include <cuda_bf16.h>
#include <cuda_fp16.h>
#include <cstdint>

// ---------------------------------------------------------------------------
// MistralAttention: fp16 HMMA projections (1-term Q/V/O, 2-term K, BK=64)
//                   RoPE fused into QKV epilogue; single transpose launch
//                   + fp16 HMMA flash attention (register-P, occ-2)
// B=1, S=2048, H=4096, NH=32, NKV=8, HD=128  (plain sm_103 target)
// ---------------------------------------------------------------------------

#define S_LEN 2048
#define HID   4096
#define NH    32
#define NKV   8
#define HD    128
#define QDIM  (NH * HD)    // 4096
#define KVDIM (NKV * HD)   // 1024
#define GK    4096

// fp16 operands
__device__ __half g_Xf16[S_LEN * HID];
__device__ __half g_Af16[S_LEN * QDIM];
__device__ __half g_Qf16[S_LEN * QDIM];
__device__ __half g_Kf16[S_LEN * KVDIM];
__device__ __half g_Vf16[S_LEN * KVDIM];

// fp16 weights, [N,K] transposed. K keeps hi+lo; Q/V/O hi only.
__device__ __half g_Wqt_hi[QDIM * GK];
__device__ __half g_Wkt_hi[KVDIM * GK], g_Wkt_lo[KVDIM * GK];
__device__ __half g_Wvt_hi[KVDIM * GK];
__device__ __half g_Wot_hi[HID * GK];

__device__ __forceinline__ uint32_t smem_u32(const void* p) {
    uint32_t a;
    asm("{ .reg .u64 t; cvta.to.shared.u64 t, %1; cvt.u32.u64 %0, t; }" : "=r"(a) : "l"(p));
    return a;
}
__device__ __forceinline__ float ex2f(float x) {
    float y;
    asm("ex2.approx.ftz.f32 %0, %1;" : "=f"(y) : "f"(x));
    return y;
}

#define CP_ASYNC16(sa, ga) \
    asm volatile("cp.async.cg.shared.global [%0], [%1], 16;" :: "r"(sa), "l"(ga))
#define CP_COMMIT() asm volatile("cp.async.commit_group;" ::: "memory")
#define CP_WAIT(n)  asm volatile("cp.async.wait_group %0;" :: "n"(n) : "memory")

#define LDMX4(r0, r1, r2, r3, a) \
    asm volatile("ldmatrix.sync.aligned.m8n8.x4.shared.b16 {%0,%1,%2,%3}, [%4];" \
                 : "=r"(r0), "=r"(r1), "=r"(r2), "=r"(r3) : "r"(a))
#define LDMX4T(r0, r1, r2, r3, a) \
    asm volatile("ldmatrix.sync.aligned.m8n8.x4.trans.shared.b16 {%0,%1,%2,%3}, [%4];" \
                 : "=r"(r0), "=r"(r1), "=r"(r2), "=r"(r3) : "r"(a))

#define MMAF16(c, a0, a1, a2, a3, b0, b1) \
    asm volatile("mma.sync.aligned.m16n8k16.row.col.f32.f16.f16.f32 " \
                 "{%0,%1,%2,%3}, {%4,%5,%6,%7}, {%8,%9}, {%0,%1,%2,%3};" \
                 : "+f"((c)[0]), "+f"((c)[1]), "+f"((c)[2]), "+f"((c)[3]) \
                 : "r"(a0), "r"(a1), "r"(a2), "r"(a3), "r"(b0), "r"(b1))

// ---------------------------------------------------------------------------
// Conversions
// ---------------------------------------------------------------------------
__global__ void tohalf_kernel(const float* __restrict__ X, __half* __restrict__ Y, int n4) {
    int i = blockIdx.x * blockDim.x + threadIdx.x;
    if (i >= n4) return;
    float4 v = ((const float4*)X)[i];
    ((__half2*)Y)[2 * i]     = __floats2half2_rn(v.x, v.y);
    ((__half2*)Y)[2 * i + 1] = __floats2half2_rn(v.z, v.w);
}

// All four weights in ONE launch: W[K,N] -> Wt hi (+ lo for K) [N,K]
// tiles: Q 128x128=16384, K 32x128=4096, V 4096, O 16384 -> 40960 blocks
#define TQ 16384
#define TK 4096
#define TV 4096

__global__ void transpose_all_kernel(const float* __restrict__ Wq,
                                     const float* __restrict__ Wk,
                                     const float* __restrict__ Wv,
                                     const float* __restrict__ Wo,
                                     __half* __restrict__ Qh,
                                     __half* __restrict__ Kh, __half* __restrict__ Kl,
                                     __half* __restrict__ Vh,
                                     __half* __restrict__ Oh) {
    __shared__ float t[32][33];
    int lin = blockIdx.x;
    const float* W;
    __half *hi, *lo = nullptr;
    int Ncols, tileidx;
    if (lin < TQ) {
        W = Wq; hi = Qh; Ncols = QDIM; tileidx = lin;
    } else if (lin < TQ + TK) {
        W = Wk; hi = Kh; lo = Kl; Ncols = KVDIM; tileidx = lin - TQ;
    } else if (lin < TQ + TK + TV) {
        W = Wv; hi = Vh; Ncols = KVDIM; tileidx = lin - TQ - TK;
    } else {
        W = Wo; hi = Oh; Ncols = HID; tileidx = lin - TQ - TK - TV;
    }
    int ntx = Ncols / 32;
    int n0 = (tileidx % ntx) * 32;
    int k0 = (tileidx / ntx) * 32;
    int tx = threadIdx.x, ty = threadIdx.y;
#pragma unroll
    for (int j = 0; j < 4; j++)
        t[ty + 8 * j][tx] = W[(size_t)(k0 + ty + 8 * j) * Ncols + n0 + tx];
    __syncthreads();
#pragma unroll
    for (int j = 0; j < 4; j++) {
        int n = n0 + ty + 8 * j;
        int k = k0 + tx;
        float v = t[tx][ty + 8 * j];
        __half h = __float2half_rn(v);
        hi[(size_t)n * GK + k] = h;
        if (lo) lo[(size_t)n * GK + k] = __float2half_rn(v - __half2float(h));
    }
}

// ---------------------------------------------------------------------------
// fp16 HMMA GEMM body: C = A*Bhi (+ A*Blo if TWO_TERM). BK=64, 2-stage, occ-2.
// OUT_MODE: 0 = fp32 gmem, 1 = fp16 gmem, 2 = fused RoPE -> fp16 gmem
// ---------------------------------------------------------------------------
#define BK       64
#define ROW_B    144              // 64 fp16 = 128B + 16B pad (conflict-free phases)
#define TILE_B   (128 * ROW_B)    // 18432
#define STAGE_B  (3 * TILE_B)     // 55296: A, Bhi, (Blo)
#define GEMM_SMEM (2 * STAGE_B)   // 110592 (x2 CTAs = 221184 <= 228KB)
#define TS_STR   132              // fp32 staging stride (words)

template <bool TWO_TERM, int OUT_MODE>
__device__ __forceinline__ void gemm_body(uint32_t sb, char* smemc,
                                          const __half* A,
                                          const __half* Bhi, const __half* Blo,
                                          float* Cf, __half* Ch,
                                          const int* pos,
                                          int N, int m0, int n0) {
    const int tid = threadIdx.x;
    const int wid = tid >> 5, lane = tid & 31;
    const int wm = wid & 3, wn = wid >> 2;

    const __half* gsrc[3] = {
        A + (size_t)m0 * GK, Bhi + (size_t)n0 * GK, Blo + (size_t)n0 * GK
    };
    const int ld_ch = tid & 7;
    const int mat = lane >> 3, r8 = lane & 7;
    const uint32_t a_off0 = (uint32_t)((wm * 32 + (mat & 1) * 8 + r8) * ROW_B + (mat >> 1) * 16);
    const uint32_t b_off0 = (uint32_t)((wn * 64 + (mat >> 1) * 8 + r8) * ROW_B + (mat & 1) * 16);

    float acc[2][8][4];
#pragma unroll
    for (int mi = 0; mi < 2; mi++)
#pragma unroll
        for (int ni = 0; ni < 8; ni++)
#pragma unroll
            for (int j = 0; j < 4; j++) acc[mi][ni][j] = 0.f;

    const int nchunk = GK / BK;
    const int niter = TWO_TERM ? 12 : 8;

    auto load_stage = [&](int c, int s) {
        const int k0 = c * BK;
#pragma unroll
        for (int it = 0; it < niter; it++) {
            int idx = it * 256 + tid;
            int tile = idx >> 10;
            int r = (idx >> 3) & 127;
            const __half* g = gsrc[tile] + (size_t)r * GK + k0 + ld_ch * 8;
            uint32_t sa = sb + s * STAGE_B + tile * TILE_B + (uint32_t)(r * ROW_B + ld_ch * 16);
            CP_ASYNC16(sa, g);
        }
        CP_COMMIT();
    };

    load_stage(0, 0);

    for (int c = 0; c < nchunk; c++) {
        const int s = c & 1;
        if (c + 1 < nchunk) {
            load_stage(c + 1, s ^ 1);
            CP_WAIT(1);
        } else {
            CP_WAIT(0);
        }
        __syncthreads();

        const uint32_t sA  = sb + s * STAGE_B;
        const uint32_t sBh = sA + TILE_B;
        const uint32_t sBl = sBh + TILE_B;

#pragma unroll
        for (int ks = 0; ks < 4; ks++) {
            const uint32_t kofs = ks * 32;
            uint32_t a[2][4];
#pragma unroll
            for (int mi = 0; mi < 2; mi++) {
                uint32_t ao = a_off0 + (uint32_t)(mi * 16 * ROW_B) + kofs;
                LDMX4(a[mi][0], a[mi][1], a[mi][2], a[mi][3], sA + ao);
            }
#pragma unroll
            for (int nq = 0; nq < 4; nq++) {
                uint32_t bo = b_off0 + (uint32_t)(nq * 16 * ROW_B) + kofs;
                uint32_t bh[2][2];
                LDMX4(bh[0][0], bh[0][1], bh[1][0], bh[1][1], sBh + bo);
                uint32_t bl[2][2];
                if (TWO_TERM) {
                    LDMX4(bl[0][0], bl[0][1], bl[1][0], bl[1][1], sBl + bo);
                }
#pragma unroll
                for (int mi = 0; mi < 2; mi++)
#pragma unroll
                    for (int nj = 0; nj < 2; nj++) {
                        int ni = nq * 2 + nj;
                        MMAF16(acc[mi][ni], a[mi][0], a[mi][1], a[mi][2], a[mi][3],
                               bh[nj][0], bh[nj][1]);
                        if (TWO_TERM) {
                            MMAF16(acc[mi][ni], a[mi][0], a[mi][1], a[mi][2], a[mi][3],
                                   bl[nj][0], bl[nj][1]);
                        }
                    }
            }
        }
        __syncthreads();
    }

    if (OUT_MODE == 0) {
#pragma unroll
        for (int mi = 0; mi < 2; mi++) {
            int row = m0 + wm * 32 + mi * 16 + (lane >> 2);
#pragma unroll
            for (int ni = 0; ni < 8; ni++) {
                int col = n0 + wn * 64 + ni * 8 + (lane & 3) * 2;
                float* p0 = Cf + (size_t)row * N + col;
                float* p1 = p0 + (size_t)8 * N;
                *(float2*)p0 = make_float2(acc[mi][ni][0], acc[mi][ni][1]);
                *(float2*)p1 = make_float2(acc[mi][ni][2], acc[mi][ni][3]);
            }
        }
    } else if (OUT_MODE == 1) {
#pragma unroll
        for (int mi = 0; mi < 2; mi++) {
            int row = m0 + wm * 32 + mi * 16 + (lane >> 2);
#pragma unroll
            for (int ni = 0; ni < 8; ni++) {
                int col = n0 + wn * 64 + ni * 8 + (lane & 3) * 2;
                __half* p0 = Ch + (size_t)row * N + col;
                __half* p1 = p0 + (size_t)8 * N;
                *(__half2*)p0 = __floats2half2_rn(acc[mi][ni][0], acc[mi][ni][1]);
                *(__half2*)p1 = __floats2half2_rn(acc[mi][ni][2], acc[mi][ni][3]);
            }
        }
    } else {
        // ---- fused RoPE epilogue: stage fp32 tile in idle pipeline smem
        float* ts = (float*)smemc;
#pragma unroll
        for (int mi = 0; mi < 2; mi++) {
            int r0 = wm * 32 + mi * 16 + (lane >> 2);
#pragma unroll
            for (int ni = 0; ni < 8; ni++) {
                int col = wn * 64 + ni * 8 + (lane & 3) * 2;
                float* p0 = ts + r0 * TS_STR + col;
                float* p1 = p0 + 8 * TS_STR;
                p0[0] = acc[mi][ni][0]; p0[1] = acc[mi][ni][1];
                p1[0] = acc[mi][ni][2]; p1[1] = acc[mi][ni][3];
            }
        }
        __syncthreads();
#pragma unroll 4
        for (int t = 0; t < 32; t++) {
            int idx = t * 256 + tid;
            int r = idx >> 6, i = idx & 63;
            float x1 = ts[r * TS_STR + i];
            float x2 = ts[r * TS_STR + i + 64];
            int srow = m0 + r;
            float inv = __expf(-(float)(2 * i) * (9.210340371976184f / 128.0f));
            float ang = (float)pos[srow] * inv;
            float sn, cs;
            __sincosf(ang, &sn, &cs);
            __half* y = Ch + (size_t)srow * N + n0 + i;
            y[0]  = __float2half_rn(x1 * cs - x2 * sn);
            y[64] = __float2half_rn(x2 * cs + x1 * sn);
        }
    }
}

// Fused QKV projection + RoPE: 48 n-slots x 16 m-tiles, L2-swizzled (GROUP_M=8).
// Slot order: K first (slowest, 2-term), then Q, then V.
__global__ __launch_bounds__(256, 2) void gemm_qkv(
    const __half* __restrict__ Xf,
    const __half* __restrict__ Wqh,
    const __half* __restrict__ Wkh, const __half* __restrict__ Wkl,
    const __half* __restrict__ Wvh,
    const int* __restrict__ pos,
    __half* __restrict__ Qh, __half* __restrict__ Kh, __half* __restrict__ Vh) {
    extern __shared__ char smem[];
    const int lin = blockIdx.y * (int)gridDim.x + blockIdx.x;
    const int W = 8 * (int)gridDim.x;
    const int g = lin / W, rem = lin % W;
    const int mt = g * 8 + (rem & 7);
    const int bx = rem >> 3;
    const int m0 = mt * 128;
    if (bx < 8) {
        gemm_body<true, 2>(smem_u32(smem), smem, Xf, Wkh, Wkl,
                           nullptr, Kh, pos, KVDIM, m0, bx * 128);
    } else if (bx < 40) {
        gemm_body<false, 2>(smem_u32(smem), smem, Xf, Wqh, Wqh,
                            nullptr, Qh, pos, QDIM, m0, (bx - 8) * 128);
    } else {
        gemm_body<false, 1>(smem_u32(smem), smem, Xf, Wvh, Wvh,
                            nullptr, Vh, nullptr, KVDIM, m0, (bx - 40) * 128);
    }
}

// O projection: 1-term fp16, fp32 out
__global__ __launch_bounds__(256, 2) void gemm_mma(
    const __half* __restrict__ A,
    const __half* __restrict__ Bhi,
    float* __restrict__ C, int N) {
    extern __shared__ char smem[];
    const int lin = blockIdx.y * (int)gridDim.x + blockIdx.x;
    const int W = 8 * (int)gridDim.x;
    const int g = lin / W, rem = lin % W;
    const int mt = g * 8 + (rem & 7);
    const int nt = rem >> 3;
    gemm_body<false, 0>(smem_u32(smem), smem, A, Bhi, Bhi,
                        C, nullptr, nullptr, N, mt * 128, nt * 128);
}

// ---------------------------------------------------------------------------
// fp16 HMMA flash attention. BM=128, BN=64, D=128, 8 warps, double-buffered,
// register-resident P, occ-2 (unchanged). Writes fp16 A.
// ---------------------------------------------------------------------------
#define QSTR 272
#define FS_Q  0
#define FS_KV 34816
#define OFF_K 0
#define OFF_V 17408
#define KVBUF 34816
#define FLASH_SMEM (FS_KV + 2 * KVBUF)       // 104448

__global__ __launch_bounds__(256, 2) void flash_mma(
    const __half* __restrict__ Qg, const __half* __restrict__ Kg,
    const __half* __restrict__ Vg,
    __half* __restrict__ Af) {
    extern __shared__ char smem[];
    const uint32_t sb = smem_u32(smem);
    const int h  = blockIdx.x;
    const int qb = (int)gridDim.y - 1 - (int)blockIdx.y;  // heavy CTAs first
    const int khd = h >> 2;
    const int tid = threadIdx.x, wid = tid >> 5, lane = tid & 31;
    const int mat = lane >> 3, r8 = lane & 7;

    // Q tile (fp16, 128 rows x 256B), own commit group
#pragma unroll
    for (int i = 0; i < 8; i++) {
        int idx = i * 256 + tid;
        int r = idx >> 4, c = idx & 15;
        const __half* g = Qg + (size_t)(qb * 128 + r) * QDIM + h * 128 + c * 8;
        CP_ASYNC16(sb + FS_Q + r * QSTR + c * 16, g);
    }
    CP_COMMIT();

    auto prefetch = [&](int u) {
        uint32_t b = sb + FS_KV + (uint32_t)(u & 1) * KVBUF;
#pragma unroll
        for (int i = 0; i < 4; i++) {
            int idx = i * 256 + tid;
            int r = idx >> 4, c = idx & 15;
            const __half* g = Kg + (size_t)(u * 64 + r) * KVDIM + khd * 128 + c * 8;
            CP_ASYNC16(b + OFF_K + r * QSTR + c * 16, g);
        }
#pragma unroll
        for (int i = 0; i < 4; i++) {
            int idx = i * 256 + tid;
            int r = idx >> 4, c = idx & 15;
            const __half* g = Vg + (size_t)(u * 64 + r) * KVDIM + khd * 128 + c * 8;
            CP_ASYNC16(b + OFF_V + r * QSTR + c * 16, g);
        }
        CP_COMMIT();
    };

    const int ntiles = 2 * qb + 2;
    prefetch(0);

    const uint32_t aQ = sb + FS_Q + (uint32_t)((wid * 16 + (mat & 1) * 8 + r8) * QSTR + (mat >> 1) * 16);
    const uint32_t k_off = (uint32_t)(((mat >> 1) * 8 + r8) * QSTR + (mat & 1) * 16);
    const uint32_t v_off = (uint32_t)(((mat & 1) * 8 + r8) * QSTR + (mat >> 1) * 16);

    float o[16][4];
#pragma unroll
    for (int nb = 0; nb < 16; nb++)
#pragma unroll
        for (int j = 0; j < 4; j++) o[nb][j] = 0.f;
    float m0 = -1e30f, m1 = -1e30f, l0 = 0.f, l1 = 0.f;

    const float scale2 = 0.12753237f;
    const int row0g = qb * 128 + wid * 16 + (lane >> 2);

    for (int t = 0; t < ntiles; t++) {
        __syncthreads();

        if (t + 1 < ntiles) {
            prefetch(t + 1);
            CP_WAIT(1);
        } else {
            CP_WAIT(0);
        }
        __syncthreads();

        const uint32_t kb = sb + FS_KV + (uint32_t)(t & 1) * KVBUF;
        const uint32_t bK = kb + OFF_K + k_off;
        const uint32_t bV = kb + OFF_V + v_off;

        float sacc[8][4];
#pragma unroll
        for (int nb = 0; nb < 8; nb++)
#pragma unroll
            for (int j = 0; j < 4; j++) sacc[nb][j] = 0.f;

#pragma unroll
        for (int ks = 0; ks < 8; ks++) {
            uint32_t q[4], kf[8][2];
            LDMX4(q[0], q[1], q[2], q[3], aQ + ks * 32);
#pragma unroll
            for (int nj = 0; nj < 4; nj++)
                LDMX4(kf[2 * nj][0], kf[2 * nj][1], kf[2 * nj + 1][0], kf[2 * nj + 1][1],
                      bK + nj * (16 * QSTR) + ks * 32);
#pragma unroll
            for (int nb = 0; nb < 8; nb++)
                MMAF16(sacc[nb], q[0], q[1], q[2], q[3], kf[nb][0], kf[nb][1]);
        }

        const bool maskt = (t >= 2 * qb);
        float mx0 = -1e30f, mx1 = -1e30f;
#pragma unroll
        for (int nb = 0; nb < 8; nb++) {
            float s0 = sacc[nb][0] * scale2, s1 = sacc[nb][1] * scale2;
            float s2 = sacc[nb][2] * scale2, s3 = sacc[nb][3] * scale2;
            if (maskt) {
                int cg = t * 64 + nb * 8 + (lane & 3) * 2;
                if (cg     > row0g)     s0 = -1e30f;
                if (cg + 1 > row0g)     s1 = -1e30f;
                if (cg     > row0g + 8) s2 = -1e30f;
                if (cg + 1 > row0g + 8) s3 = -1e30f;
            }
            sacc[nb][0] = s0; sacc[nb][1] = s1; sacc[nb][2] = s2; sacc[nb][3] = s3;
            mx0 = fmaxf(mx0, fmaxf(s0, s1));
            mx1 = fmaxf(mx1, fmaxf(s2, s3));
        }
        mx0 = fmaxf(mx0, __shfl_xor_sync(0xffffffffu, mx0, 1));
        mx0 = fmaxf(mx0, __shfl_xor_sync(0xffffffffu, mx0, 2));
        mx1 = fmaxf(mx1, __shfl_xor_sync(0xffffffffu, mx1, 1));
        mx1 = fmaxf(mx1, __shfl_xor_sync(0xffffffffu, mx1, 2));

        float mn0 = fmaxf(m0, mx0), mn1 = fmaxf(m1, mx1);
        float a0 = ex2f(m0 - mn0), a1 = ex2f(m1 - mn1);
        float sum0 = 0.f, sum1 = 0.f;

        uint32_t pa[8][2];
#pragma unroll
        for (int nb = 0; nb < 8; nb++) {
            float p0 = ex2f(sacc[nb][0] - mn0);
            float p1 = ex2f(sacc[nb][1] - mn0);
            float p2 = ex2f(sacc[nb][2] - mn1);
            float p3 = ex2f(sacc[nb][3] - mn1);
            sum0 += p0 + p1;
            sum1 += p2 + p3;
            __half2 hp01 = __floats2half2_rn(p0, p1);
            __half2 hp23 = __floats2half2_rn(p2, p3);
            pa[nb][0] = *(uint32_t*)&hp01;
            pa[nb][1] = *(uint32_t*)&hp23;
        }
        sum0 += __shfl_xor_sync(0xffffffffu, sum0, 1);
        sum0 += __shfl_xor_sync(0xffffffffu, sum0, 2);
        sum1 += __shfl_xor_sync(0xffffffffu, sum1, 1);
        sum1 += __shfl_xor_sync(0xffffffffu, sum1, 2);
        l0 = l0 * a0 + sum0; l1 = l1 * a1 + sum1;
        m0 = mn0; m1 = mn1;
#pragma unroll
        for (int nb = 0; nb < 16; nb++) {
            o[nb][0] *= a0; o[nb][1] *= a0;
            o[nb][2] *= a1; o[nb][3] *= a1;
        }

#pragma unroll
        for (int kv = 0; kv < 4; kv++) {
#pragma unroll
            for (int nj = 0; nj < 8; nj++) {
                uint32_t v0, v1, v2, v3;
                LDMX4T(v0, v1, v2, v3, bV + kv * (16 * QSTR) + nj * 32);
                MMAF16(o[2 * nj],     pa[2 * kv][0], pa[2 * kv][1],
                                      pa[2 * kv + 1][0], pa[2 * kv + 1][1], v0, v1);
                MMAF16(o[2 * nj + 1], pa[2 * kv][0], pa[2 * kv][1],
                                      pa[2 * kv + 1][0], pa[2 * kv + 1][1], v2, v3);
            }
        }
    }

    float i0 = 1.f / l0, i1 = 1.f / l1;
    size_t base0 = (size_t)row0g * QDIM + h * 128 + (lane & 3) * 2;
    size_t base1 = base0 + (size_t)8 * QDIM;
#pragma unroll
    for (int nb = 0; nb < 16; nb++) {
        *(__half2*)(Af + base0 + nb * 8) = __floats2half2_rn(o[nb][0] * i0, o[nb][1] * i0);
        *(__half2*)(Af + base1 + nb * 8) = __floats2half2_rn(o[nb][2] * i1, o[nb][3] * i1);
    }
}

// ---------------------------------------------------------------------------
// kernel_launch
// ---------------------------------------------------------------------------
extern "C" void kernel_launch(void* const* d_in, const int* in_sizes, int n_in,
                              void* d_out, int out_size) {
    (void)in_sizes; (void)n_in; (void)out_size;
    const float* X   = (const float*)d_in[0];
    const int*   pos = (const int*)d_in[2];
    const float* Wq  = (const float*)d_in[3];
    const float* Wk  = (const float*)d_in[4];
    const float* Wv  = (const float*)d_in[5];
    const float* Wo  = (const float*)d_in[6];
    float* out = (float*)d_out;

    __half *Xf, *Af, *Qf, *Kf, *Vf;
    __half *Wqh, *Wkh, *Wkl, *Wvh, *Woh;
    cudaGetSymbolAddress((void**)&Xf,  g_Xf16);
    cudaGetSymbolAddress((void**)&Af,  g_Af16);
    cudaGetSymbolAddress((void**)&Qf,  g_Qf16);
    cudaGetSymbolAddress((void**)&Kf,  g_Kf16);
    cudaGetSymbolAddress((void**)&Vf,  g_Vf16);
    cudaGetSymbolAddress((void**)&Wqh, g_Wqt_hi);
    cudaGetSymbolAddress((void**)&Wkh, g_Wkt_hi);
    cudaGetSymbolAddress((void**)&Wkl, g_Wkt_lo);
    cudaGetSymbolAddress((void**)&Wvh, g_Wvt_hi);
    cudaGetSymbolAddress((void**)&Woh, g_Wot_hi);

    // 1) hidden states -> fp16
    tohalf_kernel<<<(S_LEN * HID / 4 + 255) / 256, 256>>>(X, Xf, S_LEN * HID / 4);

    // 2) ALL weight transposes/splits in one launch
    {
        dim3 tb(32, 8);
        transpose_all_kernel<<<40960, tb>>>(Wq, Wk, Wv, Wo, Wqh, Wkh, Wkl, Wvh, Woh);
    }

    // 3) fused QKV projection + RoPE (BK=64, K-slots first)
    cudaFuncSetAttribute(gemm_qkv, cudaFuncAttributeMaxDynamicSharedMemorySize, GEMM_SMEM);
    cudaFuncSetAttribute(gemm_mma, cudaFuncAttributeMaxDynamicSharedMemorySize, GEMM_SMEM);
    gemm_qkv<<<dim3(48, S_LEN / 128), 256, GEMM_SMEM>>>(Xf, Wqh, Wkh, Wkl, Wvh,
                                                        pos, Qf, Kf, Vf);

    // 4) flash attention (fp16 HMMA, register-P, occ-2) -> fp16 A
    cudaFuncSetAttribute(flash_mma, cudaFuncAttributeMaxDynamicSharedMemorySize, FLASH_SMEM);
    flash_mma<<<dim3(NH, S_LEN / 128), 256, FLASH_SMEM>>>(Qf, Kf, Vf, Af);

    // 5) O projection (fp16 1-term HMMA, BK=64)
    gemm_mma<<<dim3(HID / 128, S_LEN / 128), 256, GEMM_SMEM>>>(Af, Woh, out, HID);
}

// round 17
// speedup vs baseline: 1.4539x; 1.4539x over previous
#include <cuda_runtime.h>
#include <cuda_bf16.h>
#include <cuda_fp16.h>
#include <cstdint>

// ---------------------------------------------------------------------------
// MistralAttention: fp16 HMMA projections (1-term Q/V/O, 2-term K, BK=64)
//                   with RoPE fused into the QKV epilogue  (R15 configuration)
//                   + fp16 HMMA flash attention (register-P, occ-2)
// B=1, S=2048, H=4096, NH=32, NKV=8, HD=128  (plain sm_103 target)
// ---------------------------------------------------------------------------

#define S_LEN 2048
#define HID   4096
#define NH    32
#define NKV   8
#define HD    128
#define QDIM  (NH * HD)    // 4096
#define KVDIM (NKV * HD)   // 1024
#define GK    4096

// fp16 operands
__device__ __half g_Xf16[S_LEN * HID];
__device__ __half g_Af16[S_LEN * QDIM];
__device__ __half g_Qf16[S_LEN * QDIM];
__device__ __half g_Kf16[S_LEN * KVDIM];
__device__ __half g_Vf16[S_LEN * KVDIM];

// fp16 weights, [N,K] transposed. K keeps hi+lo; Q/V/O hi only.
__device__ __half g_Wqt_hi[QDIM * GK];
__device__ __half g_Wkt_hi[KVDIM * GK], g_Wkt_lo[KVDIM * GK];
__device__ __half g_Wvt_hi[KVDIM * GK];
__device__ __half g_Wot_hi[HID * GK];

__device__ __forceinline__ uint32_t smem_u32(const void* p) {
    uint32_t a;
    asm("{ .reg .u64 t; cvta.to.shared.u64 t, %1; cvt.u32.u64 %0, t; }" : "=r"(a) : "l"(p));
    return a;
}
__device__ __forceinline__ float ex2f(float x) {
    float y;
    asm("ex2.approx.ftz.f32 %0, %1;" : "=f"(y) : "f"(x));
    return y;
}

#define CP_ASYNC16(sa, ga) \
    asm volatile("cp.async.cg.shared.global [%0], [%1], 16;" :: "r"(sa), "l"(ga))
#define CP_COMMIT() asm volatile("cp.async.commit_group;" ::: "memory")
#define CP_WAIT(n)  asm volatile("cp.async.wait_group %0;" :: "n"(n) : "memory")

#define LDMX4(r0, r1, r2, r3, a) \
    asm volatile("ldmatrix.sync.aligned.m8n8.x4.shared.b16 {%0,%1,%2,%3}, [%4];" \
                 : "=r"(r0), "=r"(r1), "=r"(r2), "=r"(r3) : "r"(a))
#define LDMX4T(r0, r1, r2, r3, a) \
    asm volatile("ldmatrix.sync.aligned.m8n8.x4.trans.shared.b16 {%0,%1,%2,%3}, [%4];" \
                 : "=r"(r0), "=r"(r1), "=r"(r2), "=r"(r3) : "r"(a))

#define MMAF16(c, a0, a1, a2, a3, b0, b1) \
    asm volatile("mma.sync.aligned.m16n8k16.row.col.f32.f16.f16.f32 " \
                 "{%0,%1,%2,%3}, {%4,%5,%6,%7}, {%8,%9}, {%0,%1,%2,%3};" \
                 : "+f"((c)[0]), "+f"((c)[1]), "+f"((c)[2]), "+f"((c)[3]) \
                 : "r"(a0), "r"(a1), "r"(a2), "r"(a3), "r"(b0), "r"(b1))

// ---------------------------------------------------------------------------
// Conversions
// ---------------------------------------------------------------------------
__global__ void tohalf_kernel(const float* __restrict__ X, __half* __restrict__ Y, int n4) {
    int i = blockIdx.x * blockDim.x + threadIdx.x;
    if (i >= n4) return;
    float4 v = ((const float4*)X)[i];
    ((__half2*)Y)[2 * i]     = __floats2half2_rn(v.x, v.y);
    ((__half2*)Y)[2 * i + 1] = __floats2half2_rn(v.z, v.w);
}

// W[K,N] row-major -> Wt hi (+ optional lo) [N,K], fp16 split
__global__ void transpose_split_kernel(const float* __restrict__ W,
                                       __half* __restrict__ hi,
                                       __half* __restrict__ lo,
                                       int Krows, int Ncols) {
    __shared__ float t[32][33];
    int n0 = blockIdx.x * 32, k0 = blockIdx.y * 32;
    int tx = threadIdx.x, ty = threadIdx.y;
#pragma unroll
    for (int j = 0; j < 4; j++)
        t[ty + 8 * j][tx] = W[(size_t)(k0 + ty + 8 * j) * Ncols + n0 + tx];
    __syncthreads();
#pragma unroll
    for (int j = 0; j < 4; j++) {
        int n = n0 + ty + 8 * j;
        int k = k0 + tx;
        float v = t[tx][ty + 8 * j];
        __half h = __float2half_rn(v);
        hi[(size_t)n * Krows + k] = h;
        if (lo) lo[(size_t)n * Krows + k] = __float2half_rn(v - __half2float(h));
    }
}

// ---------------------------------------------------------------------------
// fp16 HMMA GEMM body: C = A*Bhi (+ A*Blo if TWO_TERM). BK=64, 2-stage, occ-2.
// OUT_MODE: 0 = fp32 gmem, 1 = fp16 gmem, 2 = fused RoPE -> fp16 gmem
// ---------------------------------------------------------------------------
#define BK       64
#define ROW_B    144              // 64 fp16 = 128B + 16B pad (conflict-free phases)
#define TILE_B   (128 * ROW_B)    // 18432
#define STAGE_B  (3 * TILE_B)     // 55296: A, Bhi, (Blo)
#define GEMM_SMEM (2 * STAGE_B)   // 110592 (x2 CTAs = 221184 <= 228KB)
#define TS_STR   132              // fp32 staging stride (words)

template <bool TWO_TERM, int OUT_MODE>
__device__ __forceinline__ void gemm_body(uint32_t sb, char* smemc,
                                          const __half* A,
                                          const __half* Bhi, const __half* Blo,
                                          float* Cf, __half* Ch,
                                          const int* pos,
                                          int N, int m0, int n0) {
    const int tid = threadIdx.x;
    const int wid = tid >> 5, lane = tid & 31;
    const int wm = wid & 3, wn = wid >> 2;

    const __half* gsrc[3] = {
        A + (size_t)m0 * GK, Bhi + (size_t)n0 * GK, Blo + (size_t)n0 * GK
    };
    const int ld_ch = tid & 7;
    const int mat = lane >> 3, r8 = lane & 7;
    const uint32_t a_off0 = (uint32_t)((wm * 32 + (mat & 1) * 8 + r8) * ROW_B + (mat >> 1) * 16);
    const uint32_t b_off0 = (uint32_t)((wn * 64 + (mat >> 1) * 8 + r8) * ROW_B + (mat & 1) * 16);

    float acc[2][8][4];
#pragma unroll
    for (int mi = 0; mi < 2; mi++)
#pragma unroll
        for (int ni = 0; ni < 8; ni++)
#pragma unroll
            for (int j = 0; j < 4; j++) acc[mi][ni][j] = 0.f;

    const int nchunk = GK / BK;
    const int niter = TWO_TERM ? 12 : 8;

    auto load_stage = [&](int c, int s) {
        const int k0 = c * BK;
#pragma unroll
        for (int it = 0; it < niter; it++) {
            int idx = it * 256 + tid;
            int tile = idx >> 10;
            int r = (idx >> 3) & 127;
            const __half* g = gsrc[tile] + (size_t)r * GK + k0 + ld_ch * 8;
            uint32_t sa = sb + s * STAGE_B + tile * TILE_B + (uint32_t)(r * ROW_B + ld_ch * 16);
            CP_ASYNC16(sa, g);
        }
        CP_COMMIT();
    };

    load_stage(0, 0);

    for (int c = 0; c < nchunk; c++) {
        const int s = c & 1;
        if (c + 1 < nchunk) {
            load_stage(c + 1, s ^ 1);
            CP_WAIT(1);
        } else {
            CP_WAIT(0);
        }
        __syncthreads();

        const uint32_t sA  = sb + s * STAGE_B;
        const uint32_t sBh = sA + TILE_B;
        const uint32_t sBl = sBh + TILE_B;

#pragma unroll
        for (int ks = 0; ks < 4; ks++) {
            const uint32_t kofs = ks * 32;
            uint32_t a[2][4];
#pragma unroll
            for (int mi = 0; mi < 2; mi++) {
                uint32_t ao = a_off0 + (uint32_t)(mi * 16 * ROW_B) + kofs;
                LDMX4(a[mi][0], a[mi][1], a[mi][2], a[mi][3], sA + ao);
            }
#pragma unroll
            for (int nq = 0; nq < 4; nq++) {
                uint32_t bo = b_off0 + (uint32_t)(nq * 16 * ROW_B) + kofs;
                uint32_t bh[2][2];
                LDMX4(bh[0][0], bh[0][1], bh[1][0], bh[1][1], sBh + bo);
                uint32_t bl[2][2];
                if (TWO_TERM) {
                    LDMX4(bl[0][0], bl[0][1], bl[1][0], bl[1][1], sBl + bo);
                }
#pragma unroll
                for (int mi = 0; mi < 2; mi++)
#pragma unroll
                    for (int nj = 0; nj < 2; nj++) {
                        int ni = nq * 2 + nj;
                        MMAF16(acc[mi][ni], a[mi][0], a[mi][1], a[mi][2], a[mi][3],
                               bh[nj][0], bh[nj][1]);
                        if (TWO_TERM) {
                            MMAF16(acc[mi][ni], a[mi][0], a[mi][1], a[mi][2], a[mi][3],
                                   bl[nj][0], bl[nj][1]);
                        }
                    }
            }
        }
        __syncthreads();
    }

    if (OUT_MODE == 0) {
#pragma unroll
        for (int mi = 0; mi < 2; mi++) {
            int row = m0 + wm * 32 + mi * 16 + (lane >> 2);
#pragma unroll
            for (int ni = 0; ni < 8; ni++) {
                int col = n0 + wn * 64 + ni * 8 + (lane & 3) * 2;
                float* p0 = Cf + (size_t)row * N + col;
                float* p1 = p0 + (size_t)8 * N;
                *(float2*)p0 = make_float2(acc[mi][ni][0], acc[mi][ni][1]);
                *(float2*)p1 = make_float2(acc[mi][ni][2], acc[mi][ni][3]);
            }
        }
    } else if (OUT_MODE == 1) {
#pragma unroll
        for (int mi = 0; mi < 2; mi++) {
            int row = m0 + wm * 32 + mi * 16 + (lane >> 2);
#pragma unroll
            for (int ni = 0; ni < 8; ni++) {
                int col = n0 + wn * 64 + ni * 8 + (lane & 3) * 2;
                __half* p0 = Ch + (size_t)row * N + col;
                __half* p1 = p0 + (size_t)8 * N;
                *(__half2*)p0 = __floats2half2_rn(acc[mi][ni][0], acc[mi][ni][1]);
                *(__half2*)p1 = __floats2half2_rn(acc[mi][ni][2], acc[mi][ni][3]);
            }
        }
    } else {
        // ---- fused RoPE epilogue: stage fp32 tile in idle pipeline smem
        float* ts = (float*)smemc;
#pragma unroll
        for (int mi = 0; mi < 2; mi++) {
            int r0 = wm * 32 + mi * 16 + (lane >> 2);
#pragma unroll
            for (int ni = 0; ni < 8; ni++) {
                int col = wn * 64 + ni * 8 + (lane & 3) * 2;
                float* p0 = ts + r0 * TS_STR + col;
                float* p1 = p0 + 8 * TS_STR;
                p0[0] = acc[mi][ni][0]; p0[1] = acc[mi][ni][1];
                p1[0] = acc[mi][ni][2]; p1[1] = acc[mi][ni][3];
            }
        }
        __syncthreads();
#pragma unroll 4
        for (int t = 0; t < 32; t++) {
            int idx = t * 256 + tid;
            int r = idx >> 6, i = idx & 63;
            float x1 = ts[r * TS_STR + i];
            float x2 = ts[r * TS_STR + i + 64];
            int srow = m0 + r;
            float inv = __expf(-(float)(2 * i) * (9.210340371976184f / 128.0f));
            float ang = (float)pos[srow] * inv;
            float sn, cs;
            __sincosf(ang, &sn, &cs);
            __half* y = Ch + (size_t)srow * N + n0 + i;
            y[0]  = __float2half_rn(x1 * cs - x2 * sn);
            y[64] = __float2half_rn(x2 * cs + x1 * sn);
        }
    }
}

// Fused QKV projection + RoPE: 48 n-slots x 16 m-tiles, L2-swizzled (GROUP_M=8).
// R15 slot order: Q 0-31, K 32-39, V 40-47.
__global__ __launch_bounds__(256, 2) void gemm_qkv(
    const __half* __restrict__ Xf,
    const __half* __restrict__ Wqh,
    const __half* __restrict__ Wkh, const __half* __restrict__ Wkl,
    const __half* __restrict__ Wvh,
    const int* __restrict__ pos,
    __half* __restrict__ Qh, __half* __restrict__ Kh, __half* __restrict__ Vh) {
    extern __shared__ char smem[];
    const int lin = blockIdx.y * (int)gridDim.x + blockIdx.x;
    const int W = 8 * (int)gridDim.x;
    const int g = lin / W, rem = lin % W;
    const int mt = g * 8 + (rem & 7);
    const int bx = rem >> 3;
    const int m0 = mt * 128;
    if (bx < 32) {
        gemm_body<false, 2>(smem_u32(smem), smem, Xf, Wqh, Wqh,
                            nullptr, Qh, pos, QDIM, m0, bx * 128);
    } else if (bx < 40) {
        gemm_body<true, 2>(smem_u32(smem), smem, Xf, Wkh, Wkl,
                           nullptr, Kh, pos, KVDIM, m0, (bx - 32) * 128);
    } else {
        gemm_body<false, 1>(smem_u32(smem), smem, Xf, Wvh, Wvh,
                            nullptr, Vh, nullptr, KVDIM, m0, (bx - 40) * 128);
    }
}

// O projection: 1-term fp16, fp32 out
__global__ __launch_bounds__(256, 2) void gemm_mma(
    const __half* __restrict__ A,
    const __half* __restrict__ Bhi,
    float* __restrict__ C, int N) {
    extern __shared__ char smem[];
    const int lin = blockIdx.y * (int)gridDim.x + blockIdx.x;
    const int W = 8 * (int)gridDim.x;
    const int g = lin / W, rem = lin % W;
    const int mt = g * 8 + (rem & 7);
    const int nt = rem >> 3;
    gemm_body<false, 0>(smem_u32(smem), smem, A, Bhi, Bhi,
                        C, nullptr, nullptr, N, mt * 128, nt * 128);
}

// ---------------------------------------------------------------------------
// fp16 HMMA flash attention. BM=128, BN=64, D=128, 8 warps, double-buffered,
// register-resident P, occ-2. Writes fp16 A.
// ---------------------------------------------------------------------------
#define QSTR 272
#define FS_Q  0
#define FS_KV 34816
#define OFF_K 0
#define OFF_V 17408
#define KVBUF 34816
#define FLASH_SMEM (FS_KV + 2 * KVBUF)       // 104448

__global__ __launch_bounds__(256, 2) void flash_mma(
    const __half* __restrict__ Qg, const __half* __restrict__ Kg,
    const __half* __restrict__ Vg,
    __half* __restrict__ Af) {
    extern __shared__ char smem[];
    const uint32_t sb = smem_u32(smem);
    const int h  = blockIdx.x;
    const int qb = (int)gridDim.y - 1 - (int)blockIdx.y;  // heavy CTAs first
    const int khd = h >> 2;
    const int tid = threadIdx.x, wid = tid >> 5, lane = tid & 31;
    const int mat = lane >> 3, r8 = lane & 7;

    // Q tile (fp16, 128 rows x 256B), own commit group
#pragma unroll
    for (int i = 0; i < 8; i++) {
        int idx = i * 256 + tid;
        int r = idx >> 4, c = idx & 15;
        const __half* g = Qg + (size_t)(qb * 128 + r) * QDIM + h * 128 + c * 8;
        CP_ASYNC16(sb + FS_Q + r * QSTR + c * 16, g);
    }
    CP_COMMIT();

    auto prefetch = [&](int u) {
        uint32_t b = sb + FS_KV + (uint32_t)(u & 1) * KVBUF;
#pragma unroll
        for (int i = 0; i < 4; i++) {
            int idx = i * 256 + tid;
            int r = idx >> 4, c = idx & 15;
            const __half* g = Kg + (size_t)(u * 64 + r) * KVDIM + khd * 128 + c * 8;
            CP_ASYNC16(b + OFF_K + r * QSTR + c * 16, g);
        }
#pragma unroll
        for (int i = 0; i < 4; i++) {
            int idx = i * 256 + tid;
            int r = idx >> 4, c = idx & 15;
            const __half* g = Vg + (size_t)(u * 64 + r) * KVDIM + khd * 128 + c * 8;
            CP_ASYNC16(b + OFF_V + r * QSTR + c * 16, g);
        }
        CP_COMMIT();
    };

    const int ntiles = 2 * qb + 2;
    prefetch(0);

    const uint32_t aQ = sb + FS_Q + (uint32_t)((wid * 16 + (mat & 1) * 8 + r8) * QSTR + (mat >> 1) * 16);
    const uint32_t k_off = (uint32_t)(((mat >> 1) * 8 + r8) * QSTR + (mat & 1) * 16);
    const uint32_t v_off = (uint32_t)(((mat & 1) * 8 + r8) * QSTR + (mat >> 1) * 16);

    float o[16][4];
#pragma unroll
    for (int nb = 0; nb < 16; nb++)
#pragma unroll
        for (int j = 0; j < 4; j++) o[nb][j] = 0.f;
    float m0 = -1e30f, m1 = -1e30f, l0 = 0.f, l1 = 0.f;

    const float scale2 = 0.12753237f;
    const int row0g = qb * 128 + wid * 16 + (lane >> 2);

    for (int t = 0; t < ntiles; t++) {
        __syncthreads();

        if (t + 1 < ntiles) {
            prefetch(t + 1);
            CP_WAIT(1);
        } else {
            CP_WAIT(0);
        }
        __syncthreads();

        const uint32_t kb = sb + FS_KV + (uint32_t)(t & 1) * KVBUF;
        const uint32_t bK = kb + OFF_K + k_off;
        const uint32_t bV = kb + OFF_V + v_off;

        float sacc[8][4];
#pragma unroll
        for (int nb = 0; nb < 8; nb++)
#pragma unroll
            for (int j = 0; j < 4; j++) sacc[nb][j] = 0.f;

#pragma unroll
        for (int ks = 0; ks < 8; ks++) {
            uint32_t q[4], kf[8][2];
            LDMX4(q[0], q[1], q[2], q[3], aQ + ks * 32);
#pragma unroll
            for (int nj = 0; nj < 4; nj++)
                LDMX4(kf[2 * nj][0], kf[2 * nj][1], kf[2 * nj + 1][0], kf[2 * nj + 1][1],
                      bK + nj * (16 * QSTR) + ks * 32);
#pragma unroll
            for (int nb = 0; nb < 8; nb++)
                MMAF16(sacc[nb], q[0], q[1], q[2], q[3], kf[nb][0], kf[nb][1]);
        }

        const bool maskt = (t >= 2 * qb);
        float mx0 = -1e30f, mx1 = -1e30f;
#pragma unroll
        for (int nb = 0; nb < 8; nb++) {
            float s0 = sacc[nb][0] * scale2, s1 = sacc[nb][1] * scale2;
            float s2 = sacc[nb][2] * scale2, s3 = sacc[nb][3] * scale2;
            if (maskt) {
                int cg = t * 64 + nb * 8 + (lane & 3) * 2;
                if (cg     > row0g)     s0 = -1e30f;
                if (cg + 1 > row0g)     s1 = -1e30f;
                if (cg     > row0g + 8) s2 = -1e30f;
                if (cg + 1 > row0g + 8) s3 = -1e30f;
            }
            sacc[nb][0] = s0; sacc[nb][1] = s1; sacc[nb][2] = s2; sacc[nb][3] = s3;
            mx0 = fmaxf(mx0, fmaxf(s0, s1));
            mx1 = fmaxf(mx1, fmaxf(s2, s3));
        }
        mx0 = fmaxf(mx0, __shfl_xor_sync(0xffffffffu, mx0, 1));
        mx0 = fmaxf(mx0, __shfl_xor_sync(0xffffffffu, mx0, 2));
        mx1 = fmaxf(mx1, __shfl_xor_sync(0xffffffffu, mx1, 1));
        mx1 = fmaxf(mx1, __shfl_xor_sync(0xffffffffu, mx1, 2));

        float mn0 = fmaxf(m0, mx0), mn1 = fmaxf(m1, mx1);
        float a0 = ex2f(m0 - mn0), a1 = ex2f(m1 - mn1);
        float sum0 = 0.f, sum1 = 0.f;

        uint32_t pa[8][2];
#pragma unroll
        for (int nb = 0; nb < 8; nb++) {
            float p0 = ex2f(sacc[nb][0] - mn0);
            float p1 = ex2f(sacc[nb][1] - mn0);
            float p2 = ex2f(sacc[nb][2] - mn1);
            float p3 = ex2f(sacc[nb][3] - mn1);
            sum0 += p0 + p1;
            sum1 += p2 + p3;
            __half2 hp01 = __floats2half2_rn(p0, p1);
            __half2 hp23 = __floats2half2_rn(p2, p3);
            pa[nb][0] = *(uint32_t*)&hp01;
            pa[nb][1] = *(uint32_t*)&hp23;
        }
        sum0 += __shfl_xor_sync(0xffffffffu, sum0, 1);
        sum0 += __shfl_xor_sync(0xffffffffu, sum0, 2);
        sum1 += __shfl_xor_sync(0xffffffffu, sum1, 1);
        sum1 += __shfl_xor_sync(0xffffffffu, sum1, 2);
        l0 = l0 * a0 + sum0; l1 = l1 * a1 + sum1;
        m0 = mn0; m1 = mn1;
#pragma unroll
        for (int nb = 0; nb < 16; nb++) {
            o[nb][0] *= a0; o[nb][1] *= a0;
            o[nb][2] *= a1; o[nb][3] *= a1;
        }

#pragma unroll
        for (int kv = 0; kv < 4; kv++) {
#pragma unroll
            for (int nj = 0; nj < 8; nj++) {
                uint32_t v0, v1, v2, v3;
                LDMX4T(v0, v1, v2, v3, bV + kv * (16 * QSTR) + nj * 32);
                MMAF16(o[2 * nj],     pa[2 * kv][0], pa[2 * kv][1],
                                      pa[2 * kv + 1][0], pa[2 * kv + 1][1], v0, v1);
                MMAF16(o[2 * nj + 1], pa[2 * kv][0], pa[2 * kv][1],
                                      pa[2 * kv + 1][0], pa[2 * kv + 1][1], v2, v3);
            }
        }
    }

    float i0 = 1.f / l0, i1 = 1.f / l1;
    size_t base0 = (size_t)row0g * QDIM + h * 128 + (lane & 3) * 2;
    size_t base1 = base0 + (size_t)8 * QDIM;
#pragma unroll
    for (int nb = 0; nb < 16; nb++) {
        *(__half2*)(Af + base0 + nb * 8) = __floats2half2_rn(o[nb][0] * i0, o[nb][1] * i0);
        *(__half2*)(Af + base1 + nb * 8) = __floats2half2_rn(o[nb][2] * i1, o[nb][3] * i1);
    }
}

// ---------------------------------------------------------------------------
// kernel_launch
// ---------------------------------------------------------------------------
extern "C" void kernel_launch(void* const* d_in, const int* in_sizes, int n_in,
                              void* d_out, int out_size) {
    (void)in_sizes; (void)n_in; (void)out_size;
    const float* X   = (const float*)d_in[0];
    const int*   pos = (const int*)d_in[2];
    const float* Wq  = (const float*)d_in[3];
    const float* Wk  = (const float*)d_in[4];
    const float* Wv  = (const float*)d_in[5];
    const float* Wo  = (const float*)d_in[6];
    float* out = (float*)d_out;

    __half *Xf, *Af, *Qf, *Kf, *Vf;
    __half *Wqh, *Wkh, *Wkl, *Wvh, *Woh;
    cudaGetSymbolAddress((void**)&Xf,  g_Xf16);
    cudaGetSymbolAddress((void**)&Af,  g_Af16);
    cudaGetSymbolAddress((void**)&Qf,  g_Qf16);
    cudaGetSymbolAddress((void**)&Kf,  g_Kf16);
    cudaGetSymbolAddress((void**)&Vf,  g_Vf16);
    cudaGetSymbolAddress((void**)&Wqh, g_Wqt_hi);
    cudaGetSymbolAddress((void**)&Wkh, g_Wkt_hi);
    cudaGetSymbolAddress((void**)&Wkl, g_Wkt_lo);
    cudaGetSymbolAddress((void**)&Wvh, g_Wvt_hi);
    cudaGetSymbolAddress((void**)&Woh, g_Wot_hi);

    // 1) hidden states -> fp16
    tohalf_kernel<<<(S_LEN * HID / 4 + 255) / 256, 256>>>(X, Xf, S_LEN * HID / 4);

    // 2) transpose + fp16 split weights (K: hi+lo, Q/V/O: hi only)
    dim3 tb(32, 8);
    transpose_split_kernel<<<dim3(QDIM / 32, GK / 32), tb>>>(Wq, Wqh, nullptr, GK, QDIM);
    transpose_split_kernel<<<dim3(KVDIM / 32, GK / 32), tb>>>(Wk, Wkh, Wkl, GK, KVDIM);
    transpose_split_kernel<<<dim3(KVDIM / 32, GK / 32), tb>>>(Wv, Wvh, nullptr, GK, KVDIM);
    transpose_split_kernel<<<dim3(HID / 32, GK / 32), tb>>>(Wo, Woh, nullptr, GK, HID);

    // 3) fused QKV projection + RoPE (BK=64) -> fp16 Q/K/V directly
    cudaFuncSetAttribute(gemm_qkv, cudaFuncAttributeMaxDynamicSharedMemorySize, GEMM_SMEM);
    cudaFuncSetAttribute(gemm_mma, cudaFuncAttributeMaxDynamicSharedMemorySize, GEMM_SMEM);
    gemm_qkv<<<dim3(48, S_LEN / 128), 256, GEMM_SMEM>>>(Xf, Wqh, Wkh, Wkl, Wvh,
                                                        pos, Qf, Kf, Vf);

    // 4) flash attention (fp16 HMMA, register-P, occ-2) -> fp16 A
    cudaFuncSetAttribute(flash_mma, cudaFuncAttributeMaxDynamicSharedMemorySize, FLASH_SMEM);
    flash_mma<<<dim3(NH, S_LEN / 128), 256, FLASH_SMEM>>>(Qf, Kf, Vf, Af);

    // 5) O projection (fp16 1-term HMMA, BK=64)
    gemm_mma<<<dim3(HID / 128, S_LEN / 128), 256, GEMM_SMEM>>>(Af, Woh, out, HID);
}